// round 1
// baseline (speedup 1.0000x reference)
#include <cuda_runtime.h>
#include <math.h>

#define KCODES 512
#define DDIM   64
#define HDIM   64
#define LN_EPS 1e-5f

// LUTs: everything is a pure function of the token value v in [0, 512).
__device__ float  g_q_lut[KCODES * DDIM];   // codebook row chosen for each v (128 KB, L2-resident)
__device__ int    g_idx_lut[KCODES];        // argmin index for each v
__device__ double g_err_lut[KCODES];        // sum_d (codebook[idx][d] - z_v[d])^2, double-exact
__device__ int    g_cnt[KCODES];            // histogram of t

// ---------------------------------------------------------------------------
// Kernel 1: build the 512-entry LUT. One block per token value v.
// Replicates the reference fp32 math step-for-step (LN, relu, matmul,
// dist = ||z||^2 - 2 z.e + ||e||^2, first-index argmin tie-break).
// ---------------------------------------------------------------------------
__global__ void build_lut_kernel(const float* __restrict__ W1,
                                 const float* __restrict__ b1,
                                 const float* __restrict__ ln_g,
                                 const float* __restrict__ ln_b,
                                 const float* __restrict__ W2,
                                 const float* __restrict__ b2,
                                 const float* __restrict__ cb) {
    const int v   = blockIdx.x;     // 0..511
    const int tid = threadIdx.x;    // 128 threads

    __shared__ float h[HDIM];
    __shared__ float z[DDIM];
    __shared__ float s_mu, s_rstd, s_z2;
    __shared__ float s_dist[128];
    __shared__ int   s_idx[128];
    __shared__ int   s_best;

    const float norm = ((float)v / (float)(KCODES - 1)) * 2.0f - 1.0f;
    if (tid < HDIM) h[tid] = norm * W1[tid] + b1[tid];
    __syncthreads();

    if (tid == 0) {
        float s = 0.0f;
        for (int j = 0; j < HDIM; j++) s += h[j];
        const float mu = s / (float)HDIM;
        float vs = 0.0f;
        for (int j = 0; j < HDIM; j++) { float d = h[j] - mu; vs += d * d; }
        const float var = vs / (float)HDIM;
        s_mu   = mu;
        s_rstd = 1.0f / sqrtf(var + LN_EPS);
    }
    __syncthreads();

    if (tid < HDIM) {
        float x = (h[tid] - s_mu) * s_rstd * ln_g[tid] + ln_b[tid];
        h[tid] = fmaxf(x, 0.0f);                       // relu
    }
    __syncthreads();

    if (tid < DDIM) {
        float acc = 0.0f;
        for (int j = 0; j < HDIM; j++) acc += h[j] * W2[j * DDIM + tid];
        z[tid] = acc + b2[tid];
    }
    __syncthreads();

    if (tid == 0) {
        float s = 0.0f;
        for (int d = 0; d < DDIM; d++) s += z[d] * z[d];
        s_z2 = s;
    }
    __syncthreads();

    // distances to all 512 codes, 4 codes per thread
    float bestD = INFINITY;
    int   bestI = 0;
    for (int k = tid; k < KCODES; k += 128) {
        const float* e = cb + k * DDIM;
        float dot = 0.0f, e2 = 0.0f;
        for (int d = 0; d < DDIM; d++) {
            const float ev = e[d];
            dot += z[d] * ev;
            e2  += ev * ev;
        }
        const float dist = s_z2 - 2.0f * dot + e2;
        if (dist < bestD) { bestD = dist; bestI = k; }   // strict < => first index wins
    }
    s_dist[tid] = bestD;
    s_idx[tid]  = bestI;
    __syncthreads();

    for (int off = 64; off > 0; off >>= 1) {
        if (tid < off) {
            const float d2 = s_dist[tid + off];
            const int   i2 = s_idx[tid + off];
            if (d2 < s_dist[tid] || (d2 == s_dist[tid] && i2 < s_idx[tid])) {
                s_dist[tid] = d2;
                s_idx[tid]  = i2;
            }
        }
        __syncthreads();
    }

    if (tid == 0) {
        const int best = s_idx[0];
        s_best = best;
        g_idx_lut[v] = best;
        double acc = 0.0;
        for (int d = 0; d < DDIM; d++) {
            const double diff = (double)cb[best * DDIM + d] - (double)z[d];
            acc += diff * diff;
        }
        g_err_lut[v] = acc;
    }
    __syncthreads();
    if (tid < DDIM) g_q_lut[v * DDIM + tid] = cb[s_best * DDIM + tid];
}

// ---------------------------------------------------------------------------
// Kernel 2: reset histogram (graph replays must be deterministic).
// ---------------------------------------------------------------------------
__global__ void reset_cnt_kernel() {
    g_cnt[threadIdx.x] = 0;
}

// ---------------------------------------------------------------------------
// Kernel 3: histogram of token values (shared-memory privatized).
// ---------------------------------------------------------------------------
__global__ void hist_kernel(const int* __restrict__ t, int n) {
    __shared__ int sc[KCODES];
    for (int i = threadIdx.x; i < KCODES; i += blockDim.x) sc[i] = 0;
    __syncthreads();
    for (int i = blockIdx.x * blockDim.x + threadIdx.x; i < n;
         i += gridDim.x * blockDim.x) {
        atomicAdd(&sc[t[i]], 1);
    }
    __syncthreads();
    for (int i = threadIdx.x; i < KCODES; i += blockDim.x) {
        const int c = sc[i];
        if (c) atomicAdd(&g_cnt[i], c);
    }
}

// ---------------------------------------------------------------------------
// Kernel 4: scatter — the bandwidth-dominant kernel.
// One thread per float4 of q output (16 threads per token). Fully coalesced
// 16B stores; LUT gathers hit L2 (128 KB table).
// ---------------------------------------------------------------------------
__global__ void scatter_kernel(const int* __restrict__ t,
                               float4* __restrict__ q_out,
                               float* __restrict__ idx_out, int n) {
    const int i = blockIdx.x * blockDim.x + threadIdx.x;
    if (i >= n * 16) return;
    const int tok = i >> 4;
    const int d4  = i & 15;
    const int v   = __ldg(t + tok);
    const float4 val = reinterpret_cast<const float4*>(g_q_lut)[(v << 4) + d4];
    q_out[i] = val;
    if (idx_out != nullptr && d4 == 0) {
        idx_out[tok] = (float)g_idx_lut[v];
    }
}

// ---------------------------------------------------------------------------
// Kernel 5: loss = 1.25 * sum_v cnt_v * err_v / (N*D), exact via histogram.
// ---------------------------------------------------------------------------
__global__ void finalize_kernel(float* __restrict__ loss_out, int n) {
    __shared__ double acc[KCODES];
    const int tid = threadIdx.x;
    acc[tid] = (double)g_cnt[tid] * g_err_lut[tid];
    __syncthreads();
    for (int off = 256; off > 0; off >>= 1) {
        if (tid < off) acc[tid] += acc[tid + off];
        __syncthreads();
    }
    if (tid == 0) {
        loss_out[0] = (float)(1.25 * acc[0] / ((double)n * (double)DDIM));
    }
}

// ---------------------------------------------------------------------------
extern "C" void kernel_launch(void* const* d_in, const int* in_sizes, int n_in,
                              void* d_out, int out_size) {
    const int*   t    = (const int*)d_in[0];
    const float* W1   = (const float*)d_in[1];
    const float* b1   = (const float*)d_in[2];
    const float* ln_g = (const float*)d_in[3];
    const float* ln_b = (const float*)d_in[4];
    const float* W2   = (const float*)d_in[5];
    const float* b2   = (const float*)d_in[6];
    const float* cb   = (const float*)d_in[7];

    const int n = in_sizes[0];                 // N = B*T = 262144 tokens
    float* out = (float*)d_out;

    // Output layout: [ q : n*64 floats | idx : n floats | loss : 1 float ]
    const bool full = (out_size >= n * DDIM + n + 1);
    float* q_out    = out;
    float* idx_out  = full ? (out + (size_t)n * DDIM) : nullptr;
    float* loss_out = full ? (out + (size_t)n * DDIM + n) : nullptr;

    build_lut_kernel<<<KCODES, 128>>>(W1, b1, ln_g, ln_b, W2, b2, cb);
    reset_cnt_kernel<<<1, KCODES>>>();
    hist_kernel<<<256, 256>>>(t, n);

    const int total   = n * 16;
    const int threads = 256;
    scatter_kernel<<<(total + threads - 1) / threads, threads>>>(
        t, (float4*)q_out, idx_out, n);

    if (loss_out != nullptr) {
        finalize_kernel<<<1, KCODES>>>(loss_out, n);
    }
}

// round 2
// speedup vs baseline: 1.6648x; 1.6648x over previous
#include <cuda_runtime.h>
#include <math.h>

#define KCODES 512
#define DDIM   64
#define HDIM   64
#define LN_EPS 1e-5f

// LUTs: everything is a pure function of the token value v in [0, 512).
__device__ float  g_q_lut[KCODES * DDIM];   // chosen codebook row per v (128 KB)
__device__ int    g_idx_lut[KCODES];        // argmin index per v
__device__ double g_err_lut[KCODES];        // ||cb[idx] - z_v||^2 in double
__device__ int    g_cnt[KCODES];            // histogram of t

// ---------------------------------------------------------------------------
// Kernel 1: build the 512-entry LUT. One block per token value v, 128 threads.
// Codebook tiles staged through shared memory, transposed + padded:
//   smem layout sh[d*129 + k]  (d = dim 0..63, k = code-in-tile 0..127)
//   global float4 loads are coalesced; LDS writes/reads are conflict-free.
// Dot/e2 accumulation order over d is sequential per code — identical to the
// round-1 kernel that matched the reference.
// ---------------------------------------------------------------------------
__global__ void build_lut_kernel(const float* __restrict__ W1,
                                 const float* __restrict__ b1,
                                 const float* __restrict__ ln_g,
                                 const float* __restrict__ ln_b,
                                 const float* __restrict__ W2,
                                 const float* __restrict__ b2,
                                 const float* __restrict__ cb) {
    const int v   = blockIdx.x;     // 0..511
    const int tid = threadIdx.x;    // 128 threads

    __shared__ float h[HDIM];
    __shared__ float z[DDIM];
    __shared__ float s_mu, s_rstd, s_z2;
    __shared__ float s_dist[128];
    __shared__ int   s_idx[128];
    __shared__ int   s_best;
    __shared__ float sh[DDIM * 129];          // 33 KB transposed code tile

    // reset histogram slot for this v (scatter runs later in-stream)
    if (tid == 0) g_cnt[v] = 0;

    // ---- encoder: h = norm*W1 + b1 ----
    const float norm = ((float)v / (float)(KCODES - 1)) * 2.0f - 1.0f;
    if (tid < HDIM) h[tid] = norm * W1[tid] + b1[tid];
    __syncthreads();

    if (tid == 0) {
        float s = 0.0f;
        for (int j = 0; j < HDIM; j++) s += h[j];
        const float mu = s / (float)HDIM;
        float vs = 0.0f;
        for (int j = 0; j < HDIM; j++) { float d = h[j] - mu; vs += d * d; }
        s_mu   = mu;
        s_rstd = 1.0f / sqrtf(vs / (float)HDIM + LN_EPS);
    }
    __syncthreads();

    if (tid < HDIM) {
        float x = (h[tid] - s_mu) * s_rstd * ln_g[tid] + ln_b[tid];
        h[tid] = fmaxf(x, 0.0f);
    }
    __syncthreads();

    if (tid < DDIM) {
        float acc = 0.0f;
        for (int j = 0; j < HDIM; j++) acc += h[j] * W2[j * DDIM + tid];
        z[tid] = acc + b2[tid];
    }
    __syncthreads();

    if (tid == 0) {
        float s = 0.0f;
        for (int d = 0; d < DDIM; d++) s += z[d] * z[d];
        s_z2 = s;
    }
    __syncthreads();

    // ---- distances to all 512 codes, 4 tiles of 128 codes ----
    float bestD = INFINITY;
    int   bestI = 0;

    for (int tile = 0; tile < 4; tile++) {
        // load 128 codes x 64 dims, coalesced float4, store transposed
        const float4* src = reinterpret_cast<const float4*>(cb + tile * 128 * DDIM);
        #pragma unroll
        for (int j = tid; j < 128 * 16; j += 128) {   // 2048 float4 / 128 thr = 16 ea
            const int krow = j >> 4;                  // code within tile
            const int c4   = j & 15;                  // float4 column
            const float4 val = src[j];
            const int d0 = c4 * 4;
            sh[(d0 + 0) * 129 + krow] = val.x;
            sh[(d0 + 1) * 129 + krow] = val.y;
            sh[(d0 + 2) * 129 + krow] = val.z;
            sh[(d0 + 3) * 129 + krow] = val.w;
        }
        __syncthreads();

        // thread tid handles code k = tile*128 + tid  (same coverage/order as R1)
        {
            float dot = 0.0f, e2 = 0.0f;
            #pragma unroll
            for (int d = 0; d < DDIM; d++) {
                const float ev = sh[d * 129 + tid];
                dot += z[d] * ev;
                e2  += ev * ev;
            }
            const float dist = s_z2 - 2.0f * dot + e2;
            const int   k    = tile * 128 + tid;
            if (dist < bestD) { bestD = dist; bestI = k; }
        }
        __syncthreads();
    }

    // NOTE: thread tid holds best over codes {tid, 128+tid, 256+tid, 384+tid},
    // scanned in increasing k with strict < — identical tie-break to round 1.
    s_dist[tid] = bestD;
    s_idx[tid]  = bestI;
    __syncthreads();

    for (int off = 64; off > 0; off >>= 1) {
        if (tid < off) {
            const float d2 = s_dist[tid + off];
            const int   i2 = s_idx[tid + off];
            if (d2 < s_dist[tid] || (d2 == s_dist[tid] && i2 < s_idx[tid])) {
                s_dist[tid] = d2;
                s_idx[tid]  = i2;
            }
        }
        __syncthreads();
    }

    if (tid == 0) {
        const int best = s_idx[0];
        s_best = best;
        g_idx_lut[v] = best;
        double acc = 0.0;
        for (int d = 0; d < DDIM; d++) {
            const double diff = (double)cb[best * DDIM + d] - (double)z[d];
            acc += diff * diff;
        }
        g_err_lut[v] = acc;
    }
    __syncthreads();
    if (tid < DDIM) g_q_lut[v * DDIM + tid] = cb[s_best * DDIM + tid];
}

// ---------------------------------------------------------------------------
// Kernel 2: scatter + fused histogram. 16 threads per token (one float4 each,
// fully coalesced). 4 independent iterations per thread for MLP.
// ---------------------------------------------------------------------------
__global__ void scatter_kernel(const int* __restrict__ t,
                               float4* __restrict__ q_out,
                               float* __restrict__ idx_out, int n) {
    __shared__ int sc[KCODES];
    for (int i = threadIdx.x; i < KCODES; i += blockDim.x) sc[i] = 0;
    __syncthreads();

    const int total  = n * 16;
    const int stride = gridDim.x * blockDim.x;
    const float4* lut = reinterpret_cast<const float4*>(g_q_lut);

    int i = blockIdx.x * blockDim.x + threadIdx.x;

    #pragma unroll 4
    for (int it = 0; it < 4; it++) {
        if (i < total) {
            const int tok = i >> 4;
            const int d4  = i & 15;
            const int v   = __ldg(t + tok);
            q_out[i] = lut[(v << 4) + d4];
            if (d4 == 0) {
                idx_out[tok] = (float)g_idx_lut[v];
                atomicAdd(&sc[v], 1);
            }
        }
        i += stride;
    }

    __syncthreads();
    for (int j = threadIdx.x; j < KCODES; j += blockDim.x) {
        const int c = sc[j];
        if (c) atomicAdd(&g_cnt[j], c);
    }
}

// ---------------------------------------------------------------------------
// Kernel 3: loss = 1.25 * sum_v cnt_v * err_v / (N*D), exact via histogram.
// ---------------------------------------------------------------------------
__global__ void finalize_kernel(float* __restrict__ loss_out, int n) {
    __shared__ double acc[KCODES];
    const int tid = threadIdx.x;
    acc[tid] = (double)g_cnt[tid] * g_err_lut[tid];
    __syncthreads();
    for (int off = 256; off > 0; off >>= 1) {
        if (tid < off) acc[tid] += acc[tid + off];
        __syncthreads();
    }
    if (tid == 0) {
        loss_out[0] = (float)(1.25 * acc[0] / ((double)n * (double)DDIM));
    }
}

// ---------------------------------------------------------------------------
extern "C" void kernel_launch(void* const* d_in, const int* in_sizes, int n_in,
                              void* d_out, int out_size) {
    const int*   t    = (const int*)d_in[0];
    const float* W1   = (const float*)d_in[1];
    const float* b1   = (const float*)d_in[2];
    const float* ln_g = (const float*)d_in[3];
    const float* ln_b = (const float*)d_in[4];
    const float* W2   = (const float*)d_in[5];
    const float* b2   = (const float*)d_in[6];
    const float* cb   = (const float*)d_in[7];

    const int n = in_sizes[0];                 // N = B*T = 262144 tokens
    float* out = (float*)d_out;

    // Output layout: [ q : n*64 floats | idx : n floats | loss : 1 float ]
    const bool full = (out_size >= n * DDIM + n + 1);
    float* q_out    = out;
    float* idx_out  = full ? (out + (size_t)n * DDIM) : nullptr;
    float* loss_out = full ? (out + (size_t)n * DDIM + n) : nullptr;

    build_lut_kernel<<<KCODES, 128>>>(W1, b1, ln_g, ln_b, W2, b2, cb);

    const int total   = n * 16;
    const int threads = 256;
    const int iters   = 4;
    int blocks = (total + threads * iters - 1) / (threads * iters);
    scatter_kernel<<<blocks, threads>>>(t, (float4*)q_out, idx_out, n);

    if (loss_out != nullptr) {
        finalize_kernel<<<1, KCODES>>>(loss_out, n);
    }
}

// round 3
// speedup vs baseline: 2.0598x; 1.2372x over previous
#include <cuda_runtime.h>
#include <math.h>

#define KCODES 512
#define DDIM   64
#define HDIM   64
#define LN_EPS 1e-5f

#define VT     32      // token-values per dist block
#define CHUNK  64      // codes per dist block
#define NCHUNK 8       // 512 / 64
#define VTILES 16      // 512 / 32

// device scratch / LUTs
__device__ float  g_q_lut[KCODES * DDIM];     // chosen codebook row per v
__device__ float  g_idx_f[KCODES];            // argmin index per v, as float
__device__ double g_err_lut[KCODES];          // ||cb[idx]-z_v||^2, double
__device__ int    g_cnt[KCODES];              // histogram of t
__device__ float  g_z[KCODES * DDIM];         // encoder output per v
__device__ float  g_pd[KCODES * NCHUNK];      // partial best dist per (v,chunk)
__device__ int    g_pi[KCODES * NCHUNK];      // partial best idx  per (v,chunk)

// ---------------------------------------------------------------------------
// Kernel 1: fused encoder + tiled distance/argmin.
// Block = (v-tile of 32 values) x (code chunk of 64). 256 threads.
// Encoder math orders are identical to the round-2 kernel that matched the
// reference (sequential ascending loops, single fp32 accumulators).
// ---------------------------------------------------------------------------
__global__ void dist_kernel(const float* __restrict__ W1,
                            const float* __restrict__ b1,
                            const float* __restrict__ lng,
                            const float* __restrict__ lnb,
                            const float* __restrict__ W2,
                            const float* __restrict__ b2,
                            const float* __restrict__ cb) {
    __shared__ float h_sh[VT * 65];
    __shared__ float z_sh[VT * 65];
    __shared__ float cb_sh[CHUNK * DDIM];     // 16 KB, read broadcast-only
    __shared__ float s_mu[VT], s_rs[VT], s_z2[VT], s_e2[CHUNK];
    __shared__ float s_pd[VT * NCHUNK];
    __shared__ int   s_pi[VT * NCHUNK];

    const int tid   = threadIdx.x;            // 0..255
    const int vtile = blockIdx.x / NCHUNK;
    const int chunk = blockIdx.x % NCHUNK;
    const int v0    = vtile * VT;
    const int k0    = chunk * CHUNK;

    // ---- h = norm*W1 + b1 for 32 values ----
    for (int idx = tid; idx < VT * HDIM; idx += 256) {
        const int vl = idx >> 6, j = idx & 63;
        const float norm = ((float)(v0 + vl) / (float)(KCODES - 1)) * 2.0f - 1.0f;
        h_sh[vl * 65 + j] = norm * W1[j] + b1[j];
    }
    __syncthreads();

    // ---- LN stats, sequential order identical to R2 ----
    if (tid < VT) {
        float s = 0.0f;
        for (int j = 0; j < HDIM; j++) s += h_sh[tid * 65 + j];
        const float mu = s / (float)HDIM;
        float vs = 0.0f;
        for (int j = 0; j < HDIM; j++) {
            const float d = h_sh[tid * 65 + j] - mu;
            vs += d * d;
        }
        s_mu[tid] = mu;
        s_rs[tid] = 1.0f / sqrtf(vs / (float)HDIM + LN_EPS);
    }
    __syncthreads();

    // ---- LN + relu ----
    for (int idx = tid; idx < VT * HDIM; idx += 256) {
        const int vl = idx >> 6, j = idx & 63;
        float x = (h_sh[vl * 65 + j] - s_mu[vl]) * s_rs[vl] * lng[j] + lnb[j];
        h_sh[vl * 65 + j] = fmaxf(x, 0.0f);
    }
    __syncthreads();

    // ---- z = h @ W2 + b2 (sequential j, same order as R2) ----
    for (int idx = tid; idx < VT * DDIM; idx += 256) {
        const int vl = idx >> 6, d = idx & 63;
        float acc = 0.0f;
        for (int j = 0; j < HDIM; j++)
            acc += h_sh[vl * 65 + j] * W2[j * DDIM + d];
        z_sh[vl * 65 + d] = acc + b2[d];
    }
    __syncthreads();

    // ---- z2 (sequential d) ----
    if (tid < VT) {
        float s = 0.0f;
        for (int d = 0; d < DDIM; d++) {
            const float zz = z_sh[tid * 65 + d];
            s += zz * zz;
        }
        s_z2[tid] = s;
    }

    // ---- stage codebook chunk (coalesced float4) ----
    {
        const float4* src = reinterpret_cast<const float4*>(cb + (size_t)k0 * DDIM);
        float4* dst = reinterpret_cast<float4*>(cb_sh);
        for (int j = tid; j < CHUNK * (DDIM / 4); j += 256) dst[j] = src[j];
    }

    // ---- e2 per code (sequential d order, from global) ----
    if (tid < CHUNK) {
        const float4* e = reinterpret_cast<const float4*>(cb + (size_t)(k0 + tid) * DDIM);
        float acc = 0.0f;
        #pragma unroll
        for (int i = 0; i < DDIM / 4; i++) {
            const float4 c = e[i];
            acc += c.x * c.x;
            acc += c.y * c.y;
            acc += c.z * c.z;
            acc += c.w * c.w;
        }
        s_e2[tid] = acc;
    }

    // chunk==0 blocks persist z for the error computation later
    __syncthreads();
    if (chunk == 0) {
        for (int idx = tid; idx < VT * DDIM; idx += 256) {
            const int vl = idx >> 6, d = idx & 63;
            g_z[(v0 + vl) * DDIM + d] = z_sh[vl * 65 + d];
        }
    }

    // ---- main: thread (vl, kg) handles 8 contiguous codes ----
    const int vl = tid & 31;
    const int kg = tid >> 5;

    float z[DDIM];
    #pragma unroll
    for (int d = 0; d < DDIM; d++) z[d] = z_sh[vl * 65 + d];
    const float z2 = s_z2[vl];

    float bestD = INFINITY;
    int   bestI = 0;
    for (int c = 0; c < 8; c++) {
        const int kl = kg * 8 + c;
        const float4* e = reinterpret_cast<const float4*>(cb_sh + kl * DDIM);
        float dot = 0.0f;
        #pragma unroll
        for (int i = 0; i < DDIM / 4; i++) {
            const float4 cc = e[i];
            dot += z[4 * i + 0] * cc.x;
            dot += z[4 * i + 1] * cc.y;
            dot += z[4 * i + 2] * cc.z;
            dot += z[4 * i + 3] * cc.w;
        }
        const float dist = z2 - 2.0f * dot + s_e2[kl];
        if (dist < bestD) { bestD = dist; bestI = k0 + kl; }  // strict <, ascending k
    }
    s_pd[vl * NCHUNK + kg] = bestD;
    s_pi[vl * NCHUNK + kg] = bestI;
    __syncthreads();

    // combine across kg in ascending order (first-min tie-break preserved)
    if (tid < VT) {
        float bd = INFINITY;
        int   bi = 0;
        for (int g = 0; g < NCHUNK; g++) {
            const float d2 = s_pd[tid * NCHUNK + g];
            if (d2 < bd) { bd = d2; bi = s_pi[tid * NCHUNK + g]; }
        }
        g_pd[(v0 + tid) * NCHUNK + chunk] = bd;
        g_pi[(v0 + tid) * NCHUNK + chunk] = bi;
    }
}

// ---------------------------------------------------------------------------
// Kernel 2: combine chunk partials, fill LUT, compute per-v double error,
// reset histogram. Grid = 512 blocks x 64 threads.
// ---------------------------------------------------------------------------
__global__ void lutfill_kernel(const float* __restrict__ cb) {
    const int v   = blockIdx.x;
    const int tid = threadIdx.x;
    __shared__ int s_best;

    if (tid == 0) {
        float bd = INFINITY;
        int   bi = 0;
        for (int c = 0; c < NCHUNK; c++) {            // ascending chunk = ascending k
            const float d = g_pd[v * NCHUNK + c];
            if (d < bd) { bd = d; bi = g_pi[v * NCHUNK + c]; }
        }
        s_best = bi;
        g_idx_f[v] = (float)bi;
        g_cnt[v] = 0;
    }
    __syncthreads();

    const int best = s_best;
    g_q_lut[v * DDIM + tid] = cb[(size_t)best * DDIM + tid];

    if (tid == 0) {
        double acc = 0.0;
        for (int d = 0; d < DDIM; d++) {
            const double diff = (double)cb[(size_t)best * DDIM + d]
                              - (double)g_z[v * DDIM + d];
            acc += diff * diff;
        }
        g_err_lut[v] = acc;
    }
}

// ---------------------------------------------------------------------------
// Kernel 3: scatter + fused histogram. One thread per output float4.
// Unroll 8 with explicit load phase then store phase for MLP.
// ---------------------------------------------------------------------------
#define SC_UNROLL 8
__global__ void scatter_kernel(const int* __restrict__ t,
                               float4* __restrict__ q_out,
                               float* __restrict__ idx_out, int n) {
    __shared__ int sc[KCODES];
    for (int i = threadIdx.x; i < KCODES; i += blockDim.x) sc[i] = 0;
    __syncthreads();

    const int total  = n * 16;
    const int stride = gridDim.x * blockDim.x;
    const int i0     = blockIdx.x * blockDim.x + threadIdx.x;
    const float4* lut = reinterpret_cast<const float4*>(g_q_lut);

    int    vs[SC_UNROLL];
    float4 vals[SC_UNROLL];

    #pragma unroll
    for (int j = 0; j < SC_UNROLL; j++) {
        const int i = i0 + j * stride;
        if (i < total) {
            const int v = __ldg(t + (i >> 4));
            vs[j]   = v;
            vals[j] = __ldg(&lut[(v << 4) + (i & 15)]);
        } else {
            vs[j] = -1;
        }
    }

    #pragma unroll
    for (int j = 0; j < SC_UNROLL; j++) {
        const int i = i0 + j * stride;
        if (vs[j] >= 0) {
            __stcs(&q_out[i], vals[j]);
            if ((i & 15) == 0) {
                if (idx_out != nullptr) idx_out[i >> 4] = g_idx_f[vs[j]];
                atomicAdd(&sc[vs[j]], 1);
            }
        }
    }

    __syncthreads();
    for (int j = threadIdx.x; j < KCODES; j += blockDim.x) {
        const int c = sc[j];
        if (c) atomicAdd(&g_cnt[j], c);
    }
}

// ---------------------------------------------------------------------------
// Kernel 4: loss = 1.25 * sum_v cnt_v * err_v / (N*D), exact via histogram.
// ---------------------------------------------------------------------------
__global__ void finalize_kernel(float* __restrict__ loss_out, int n) {
    __shared__ double acc[KCODES];
    const int tid = threadIdx.x;
    acc[tid] = (double)g_cnt[tid] * g_err_lut[tid];
    __syncthreads();
    for (int off = 256; off > 0; off >>= 1) {
        if (tid < off) acc[tid] += acc[tid + off];
        __syncthreads();
    }
    if (tid == 0) {
        loss_out[0] = (float)(1.25 * acc[0] / ((double)n * (double)DDIM));
    }
}

// ---------------------------------------------------------------------------
extern "C" void kernel_launch(void* const* d_in, const int* in_sizes, int n_in,
                              void* d_out, int out_size) {
    const int*   t    = (const int*)d_in[0];
    const float* W1   = (const float*)d_in[1];
    const float* b1   = (const float*)d_in[2];
    const float* lng  = (const float*)d_in[3];
    const float* lnb  = (const float*)d_in[4];
    const float* W2   = (const float*)d_in[5];
    const float* b2   = (const float*)d_in[6];
    const float* cb   = (const float*)d_in[7];

    const int n = in_sizes[0];                 // N = B*T = 262144 tokens
    float* out = (float*)d_out;

    // Output layout: [ q : n*64 floats | idx : n floats | loss : 1 float ]
    const bool full = (out_size >= n * DDIM + n + 1);
    float* q_out    = out;
    float* idx_out  = full ? (out + (size_t)n * DDIM) : nullptr;
    float* loss_out = full ? (out + (size_t)n * DDIM + n) : nullptr;

    dist_kernel<<<VTILES * NCHUNK, 256>>>(W1, b1, lng, lnb, W2, b2, cb);
    lutfill_kernel<<<KCODES, DDIM>>>(cb);

    const int total   = n * 16;
    const int threads = 256;
    int blocks = (total + threads * SC_UNROLL - 1) / (threads * SC_UNROLL);
    scatter_kernel<<<blocks, threads>>>(t, (float4*)q_out, idx_out, n);

    if (loss_out != nullptr) {
        finalize_kernel<<<1, KCODES>>>(loss_out, n);
    }
}